// round 10
// baseline (speedup 1.0000x reference)
#include <cuda_runtime.h>

// Problem constants
#define BB   256
#define TTOT 16384
#define ALPHA_F 0.95f

// LIF chunking (verified exact): 64 chunks of 256, warm-up 512
#define LCHUNK 256
#define WARM   512
#define NCHUNK (TTOT / LCHUNK)   // 64

// lif smem tiling: u tile = [3ch][32 t][128 b pad 129], 4-deep pipeline
#define TTILE 32
#define BPAD  129
#define CHSZ  (TTILE * BPAD)            // 4128 floats
#define UBUF  (3 * CHSZ)                // 12384 floats = 49536 B
#define MROWS 384                       // 3ch * 128b mask words per tile
#define LIF_SMEM_BYTES (4 * UBUF * 4 + 2 * MROWS * 4)   // 201216 B

// ---------------------------------------------------------------------------
// Kernel 1: causal conv (measured ~21.6us).
// ---------------------------------------------------------------------------
__global__ __launch_bounds__(512) void conv_kernel(
    const float* __restrict__ x,
    const float* __restrict__ w0,
    const float* __restrict__ w1,
    const float* __restrict__ w2,
    float* __restrict__ u)
{
    __shared__ float xs[2080];

    const int b    = blockIdx.x;
    const int tile = blockIdx.y;
    const int t0   = tile * 2048;
    const float* xb = x + (size_t)b * TTOT;

    for (int i = threadIdx.x; i < 2080; i += 512) {
        int gi = t0 + i - 31;
        xs[i] = (gi >= 0 && gi < TTOT) ? xb[gi] : 0.0f;
    }

    float W2[32], W1[16], W0[8];
#pragma unroll
    for (int i = 0; i < 32; i++) W2[i] = w2[i] * 0.1767766952966369f;
#pragma unroll
    for (int i = 0; i < 16; i++) W1[i] = w1[i] * 0.25f;
#pragma unroll
    for (int i = 0; i < 8;  i++) W0[i] = w0[i] * 0.3535533905932738f;

    __syncthreads();

    const int tt0 = threadIdx.x * 4;

    float xv[36];
#pragma unroll
    for (int q = 0; q < 9; q++) {
        float4 v = *reinterpret_cast<const float4*>(&xs[tt0 + 4 * q]);
        xv[4 * q + 0] = v.x; xv[4 * q + 1] = v.y;
        xv[4 * q + 2] = v.z; xv[4 * q + 3] = v.w;
    }

    float a0[4] = {0.f, 0.f, 0.f, 0.f};
    float a1[4] = {0.f, 0.f, 0.f, 0.f};
    float a2[4] = {0.f, 0.f, 0.f, 0.f};

#pragma unroll
    for (int kk = 0; kk < 32; kk++)
#pragma unroll
        for (int r = 0; r < 4; r++)
            a2[r] = fmaf(W2[kk], xv[kk + r], a2[r]);
#pragma unroll
    for (int kk = 0; kk < 16; kk++)
#pragma unroll
        for (int r = 0; r < 4; r++)
            a1[r] = fmaf(W1[kk], xv[16 + kk + r], a1[r]);
#pragma unroll
    for (int kk = 0; kk < 8; kk++)
#pragma unroll
        for (int r = 0; r < 4; r++)
            a0[r] = fmaf(W0[kk], xv[24 + kk + r], a0[r]);

    const int t = t0 + tt0;
    float* ub = u + (size_t)b * 3 * TTOT;
    *reinterpret_cast<float4*>(ub + 0 * TTOT + t) = make_float4(a0[0], a0[1], a0[2], a0[3]);
    *reinterpret_cast<float4*>(ub + 1 * TTOT + t) = make_float4(a1[0], a1[1], a1[2], a1[3]);
    *reinterpret_cast<float4*>(ub + 2 * TTOT + t) = make_float4(a2[0], a2[1], a2[2], a2[3]);
}

// ---------------------------------------------------------------------------
// Kernel 2: LIF + WTA scan, warp-specialized, bitmask spikes, 4-deep pipeline.
// Block = 256 thr: warps 0-3 consumers (pure scan), warps 4-7 producers.
// Producer iter i: STS tile i+2 (regs loaded at iter i-1, latency hidden),
// LDG tile i+3 into regs, drain masks of tile i-1.
// Grid = 128 = (chunk 0..63) x (batch half).
// ---------------------------------------------------------------------------
__global__ __launch_bounds__(256) void lif_kernel(
    const float* __restrict__ u,
    float* __restrict__ s)
{
    extern __shared__ float sm[];
    float* ubase = sm;                               // 4 x UBUF
    unsigned* mbuf[2] = { reinterpret_cast<unsigned*>(sm + 4 * UBUF),
                          reinterpret_cast<unsigned*>(sm + 4 * UBUF) + MROWS };

    const int tid   = threadIdx.x;
    const int c     = (int)blockIdx.x >> 1;
    const int bbase = ((int)blockIdx.x & 1) << 7;

    const int commit = c * LCHUNK;
    int start = commit - WARM; if (start < 0) start = 0;
    const int ntiles    = (commit + LCHUNK - start) >> 5;   // 8..24
    const int commit_i0 = (commit - start) >> 5;

    const bool is_prod = (tid >= 128);
    const int  ptid    = tid & 127;

#define LD_BATCH(t0v, h, pf)                                                   \
    {                                                                          \
        _Pragma("unroll")                                                      \
        for (int j = 0; j < 12; j++) {                                         \
            int idx = ((h) * 12 + j) * 128 + ptid;                             \
            int o   = idx & 7;                                                 \
            int row = idx >> 3;                                                \
            int ch  = row >> 7;                                                \
            int br  = row & 127;                                               \
            const float* g = u + ((size_t)((bbase + br) * 3 + ch)) * TTOT      \
                               + (t0v) + 4 * o;                                \
            pf[j] = *reinterpret_cast<const float4*>(g);                       \
        }                                                                      \
    }
#define ST_BATCH(dst, h, pf)                                                   \
    {                                                                          \
        _Pragma("unroll")                                                      \
        for (int j = 0; j < 12; j++) {                                         \
            int idx = ((h) * 12 + j) * 128 + ptid;                             \
            int o   = idx & 7;                                                 \
            int row = idx >> 3;                                                \
            int ch  = row >> 7;                                                \
            int br  = row & 127;                                               \
            float* p = (dst) + ch * CHSZ + (4 * o) * BPAD + br;                \
            p[0 * BPAD] = pf[j].x;                                             \
            p[1 * BPAD] = pf[j].y;                                             \
            p[2 * BPAD] = pf[j].z;                                             \
            p[3 * BPAD] = pf[j].w;                                             \
        }                                                                      \
    }
    // mask drain: tile spikes = 384 rows x 32 t = 3072 float4, 24 per thread.
#define DRAIN_MASKS(mb, t0v)                                                   \
    {                                                                          \
        _Pragma("unroll")                                                      \
        for (int q = 0; q < 24; q++) {                                         \
            int idx = q * 128 + ptid;                                          \
            int o   = idx & 7;                                                 \
            int row = idx >> 3;                                                \
            int ch  = row >> 7;                                                \
            int br  = row & 127;                                               \
            unsigned m = (mb)[row];                                            \
            float4 v;                                                          \
            v.x = (m >> (4 * o + 0)) & 1u ? 1.0f : 0.0f;                       \
            v.y = (m >> (4 * o + 1)) & 1u ? 1.0f : 0.0f;                       \
            v.z = (m >> (4 * o + 2)) & 1u ? 1.0f : 0.0f;                       \
            v.w = (m >> (4 * o + 3)) & 1u ? 1.0f : 0.0f;                       \
            float* g = s + ((size_t)((bbase + br) * 3 + ch)) * TTOT            \
                         + (t0v) + 4 * o;                                      \
            *reinterpret_cast<float4*>(g) = v;                                 \
        }                                                                      \
    }

    float4 pfa[12], pfb[12];   // producer's in-flight tile (i+3 at iter i)

    // prime: stage tiles 0,1 into ubuf0/1; pre-load tile 2 into regs
    if (is_prod) {
        LD_BATCH(start, 0, pfa);
        LD_BATCH(start, 1, pfb);
        ST_BATCH(ubase + 0 * UBUF, 0, pfa);
        ST_BATCH(ubase + 0 * UBUF, 1, pfb);
        if (ntiles > 1) {
            LD_BATCH(start + TTILE, 0, pfa);
            LD_BATCH(start + TTILE, 1, pfb);
            ST_BATCH(ubase + 1 * UBUF, 0, pfa);
            ST_BATCH(ubase + 1 * UBUF, 1, pfb);
        }
        if (ntiles > 2) {
            LD_BATCH(start + 2 * TTILE, 0, pfa);
            LD_BATCH(start + 2 * TTILE, 1, pfb);
        }
    }
    __syncthreads();

    float y0 = 0.f, y1 = 0.f, y2 = 0.f;

    for (int i = 0; i < ntiles; i++) {
        const int t0 = start + i * TTILE;

        if (!is_prod) {
            // -------- consumer: pure scan of tile i --------
            const float* Pc = ubase + (size_t)(i & 3) * UBUF + ptid;
            if (i >= commit_i0) {
                unsigned m0 = 0u, m1 = 0u, m2 = 0u;
#pragma unroll
                for (int t = 0; t < TTILE; t++) {
                    const float u0 = Pc[0 * CHSZ + t * BPAD];
                    const float u1 = Pc[1 * CHSZ + t * BPAD];
                    const float u2 = Pc[2 * CHSZ + t * BPAD];
                    const float w0v = fmaf(ALPHA_F, y0, u0);
                    const float w1v = fmaf(ALPHA_F, y1, u1);
                    const float w2v = fmaf(ALPHA_F, y2, u2);
                    const bool g01 = (w0v >= w1v), g02 = (w0v >= w2v), g12 = (w1v >= w2v);
                    const bool f0 = g01 & g02 & (w0v >= 1.0f);
                    const bool f1 = (!g01) & g12 & (w1v >= 1.0f);
                    const bool f2 = (!g02) & (!g12) & (w2v >= 1.0f);
                    y0 = w0v - (f0 ? 1.0f : 0.0f);
                    y1 = w1v - (f1 ? 1.0f : 0.0f);
                    y2 = w2v - (f2 ? 1.0f : 0.0f);
                    m0 |= f0 ? (1u << t) : 0u;
                    m1 |= f1 ? (1u << t) : 0u;
                    m2 |= f2 ? (1u << t) : 0u;
                }
                unsigned* mb = mbuf[i & 1];
                mb[0 * 128 + ptid] = m0;
                mb[1 * 128 + ptid] = m1;
                mb[2 * 128 + ptid] = m2;
            } else {
#pragma unroll
                for (int t = 0; t < TTILE; t++) {
                    const float u0 = Pc[0 * CHSZ + t * BPAD];
                    const float u1 = Pc[1 * CHSZ + t * BPAD];
                    const float u2 = Pc[2 * CHSZ + t * BPAD];
                    const float w0v = fmaf(ALPHA_F, y0, u0);
                    const float w1v = fmaf(ALPHA_F, y1, u1);
                    const float w2v = fmaf(ALPHA_F, y2, u2);
                    const bool g01 = (w0v >= w1v), g02 = (w0v >= w2v), g12 = (w1v >= w2v);
                    const bool f0 = g01 & g02 & (w0v >= 1.0f);
                    const bool f1 = (!g01) & g12 & (w1v >= 1.0f);
                    const bool f2 = (!g02) & (!g12) & (w2v >= 1.0f);
                    y0 = w0v - (f0 ? 1.0f : 0.0f);
                    y1 = w1v - (f1 ? 1.0f : 0.0f);
                    y2 = w2v - (f2 ? 1.0f : 0.0f);
                }
            }
        } else {
            // -------- producer --------
            // 1) STS tile i+2 from regs loaded at iter i-1 (data already arrived)
            if (i + 2 < ntiles) {
                float* Bn = ubase + (size_t)((i + 2) & 3) * UBUF;
                ST_BATCH(Bn, 0, pfa);
                ST_BATCH(Bn, 1, pfb);
            }
            // 2) issue LDG for tile i+3 (regs free after STS reads; arrives iter i+1)
            if (i + 3 < ntiles) {
                LD_BATCH(t0 + 3 * TTILE, 0, pfa);
                LD_BATCH(t0 + 3 * TTILE, 1, pfb);
            }
            // 3) drain masks of tile i-1 (overlaps everything)
            if (i >= 1 && i - 1 >= commit_i0)
                DRAIN_MASKS(mbuf[(i - 1) & 1], t0 - TTILE);
        }

        __syncthreads();
    }

    // epilogue: drain last commit tile's masks
    if (is_prod) {
        const int ilast = ntiles - 1;
        DRAIN_MASKS(mbuf[ilast & 1], start + ilast * TTILE);
    }
#undef LD_BATCH
#undef ST_BATCH
#undef DRAIN_MASKS
}

// ---------------------------------------------------------------------------
// Launch.
// ---------------------------------------------------------------------------
extern "C" void kernel_launch(void* const* d_in, const int* in_sizes, int n_in,
                              void* d_out, int out_size)
{
    const float* x  = (const float*)d_in[0];
    const float* w0 = (const float*)d_in[1];
    const float* w1 = (const float*)d_in[2];
    const float* w2 = (const float*)d_in[3];

    float* u = (float*)d_out;
    float* s = u + (size_t)BB * 3 * TTOT;

    cudaFuncSetAttribute(lif_kernel, cudaFuncAttributeMaxDynamicSharedMemorySize,
                         LIF_SMEM_BYTES);

    dim3 cgrid(BB, TTOT / 2048);
    conv_kernel<<<cgrid, 512>>>(x, w0, w1, w2, u);

    lif_kernel<<<NCHUNK * 2, 256, LIF_SMEM_BYTES>>>(u, s);
}

// round 11
// speedup vs baseline: 1.0303x; 1.0303x over previous
#include <cuda_runtime.h>

// Problem constants
#define BB   256
#define TTOT 16384
#define ALPHA_F 0.95f

// LIF chunking (verified exact): 64 chunks of 256, warm-up 512
#define LCHUNK 256
#define WARM   512
#define NCHUNK (TTOT / LCHUNK)   // 64

// lif smem tiling: tile rows rr = br*3+ch (b-major), 36 words (144B) per row.
// 144B row: 16B-aligned for STS.128; lane stride 108 words -> conflict-free LDS.128.
#define TTILE 32
#define ROWW  36
#define NROW  384                       // 128 b x 3 ch
#define UBUF  (NROW * ROWW)             // 13824 floats = 55296 B
#define LIF_SMEM_BYTES (2 * UBUF * 4 + 2 * NROW * 4)   // 113664 B

// ---------------------------------------------------------------------------
// Kernel 1: causal conv (measured ~21.6us).
// ---------------------------------------------------------------------------
__global__ __launch_bounds__(512) void conv_kernel(
    const float* __restrict__ x,
    const float* __restrict__ w0,
    const float* __restrict__ w1,
    const float* __restrict__ w2,
    float* __restrict__ u)
{
    __shared__ float xs[2080];

    const int b    = blockIdx.x;
    const int tile = blockIdx.y;
    const int t0   = tile * 2048;
    const float* xb = x + (size_t)b * TTOT;

    for (int i = threadIdx.x; i < 2080; i += 512) {
        int gi = t0 + i - 31;
        xs[i] = (gi >= 0 && gi < TTOT) ? xb[gi] : 0.0f;
    }

    float W2[32], W1[16], W0[8];
#pragma unroll
    for (int i = 0; i < 32; i++) W2[i] = w2[i] * 0.1767766952966369f;
#pragma unroll
    for (int i = 0; i < 16; i++) W1[i] = w1[i] * 0.25f;
#pragma unroll
    for (int i = 0; i < 8;  i++) W0[i] = w0[i] * 0.3535533905932738f;

    __syncthreads();

    const int tt0 = threadIdx.x * 4;

    float xv[36];
#pragma unroll
    for (int q = 0; q < 9; q++) {
        float4 v = *reinterpret_cast<const float4*>(&xs[tt0 + 4 * q]);
        xv[4 * q + 0] = v.x; xv[4 * q + 1] = v.y;
        xv[4 * q + 2] = v.z; xv[4 * q + 3] = v.w;
    }

    float a0[4] = {0.f, 0.f, 0.f, 0.f};
    float a1[4] = {0.f, 0.f, 0.f, 0.f};
    float a2[4] = {0.f, 0.f, 0.f, 0.f};

#pragma unroll
    for (int kk = 0; kk < 32; kk++)
#pragma unroll
        for (int r = 0; r < 4; r++)
            a2[r] = fmaf(W2[kk], xv[kk + r], a2[r]);
#pragma unroll
    for (int kk = 0; kk < 16; kk++)
#pragma unroll
        for (int r = 0; r < 4; r++)
            a1[r] = fmaf(W1[kk], xv[16 + kk + r], a1[r]);
#pragma unroll
    for (int kk = 0; kk < 8; kk++)
#pragma unroll
        for (int r = 0; r < 4; r++)
            a0[r] = fmaf(W0[kk], xv[24 + kk + r], a0[r]);

    const int t = t0 + tt0;
    float* ub = u + (size_t)b * 3 * TTOT;
    *reinterpret_cast<float4*>(ub + 0 * TTOT + t) = make_float4(a0[0], a0[1], a0[2], a0[3]);
    *reinterpret_cast<float4*>(ub + 1 * TTOT + t) = make_float4(a1[0], a1[1], a1[2], a1[3]);
    *reinterpret_cast<float4*>(ub + 2 * TTOT + t) = make_float4(a2[0], a2[1], a2[2], a2[3]);
}

// ---------------------------------------------------------------------------
// Kernel 2: LIF + WTA scan, warp-specialized, vectorized address-free staging.
// Block = 256 thr: warps 0-3 consumers, warps 4-7 producers.
// Smem tile rows rr = br*3+ch map 1:1 to global u/s rows bbase*3+rr, so the
// producer's 24 LDG.128/STS.128 use compile-constant strides only.
// Grid = 128 = (chunk 0..63) x (batch half).
// ---------------------------------------------------------------------------
__global__ __launch_bounds__(256) void lif_kernel(
    const float* __restrict__ u,
    float* __restrict__ s)
{
    extern __shared__ float sm[];
    float*    ub0 = sm;
    float*    ub1 = sm + UBUF;
    unsigned* mb0 = reinterpret_cast<unsigned*>(sm + 2 * UBUF);
    unsigned* mb1 = mb0 + NROW;

    const int tid   = threadIdx.x;
    const int c     = (int)blockIdx.x >> 1;
    const int bbase = ((int)blockIdx.x & 1) << 7;

    const int commit = c * LCHUNK;
    int start = commit - WARM; if (start < 0) start = 0;
    const int ntiles = (commit + LCHUNK - start) >> 5;   // 8..24
    const int ci0    = (commit - start) >> 5;

    const bool is_prod = (tid >= 128);
    const int  ptid    = tid & 127;

    // producer-fixed geometry
    const int p8 = ptid >> 3;       // row group 0..15
    const int o  = ptid & 7;        // float4 slot in t
    const int sh = 4 * o;
    const float* gb = u + (size_t)(bbase * 3 + p8) * TTOT + 4 * o;
    float*       sg = s + (size_t)(bbase * 3 + p8) * TTOT + 4 * o;

    float4 pa[12], pb[12];
    float y0 = 0.f, y1 = 0.f, y2 = 0.f;

#define P_LD(tv)                                                               \
    {                                                                          \
        _Pragma("unroll")                                                      \
        for (int j = 0; j < 12; j++)                                           \
            pa[j] = *reinterpret_cast<const float4*>(                          \
                gb + (size_t)(j * 16) * TTOT + (tv));                          \
        _Pragma("unroll")                                                      \
        for (int j = 0; j < 12; j++)                                           \
            pb[j] = *reinterpret_cast<const float4*>(                          \
                gb + (size_t)((j + 12) * 16) * TTOT + (tv));                   \
    }
#define P_ST(buf)                                                              \
    {                                                                          \
        float* sp = (buf) + p8 * ROWW + 4 * o;                                 \
        _Pragma("unroll")                                                      \
        for (int j = 0; j < 12; j++)                                           \
            *reinterpret_cast<float4*>(sp + j * 16 * ROWW) = pa[j];            \
        _Pragma("unroll")                                                      \
        for (int j = 0; j < 12; j++)                                           \
            *reinterpret_cast<float4*>(sp + (j + 12) * 16 * ROWW) = pb[j];     \
    }
#define P_DRAIN(mbp, tv)                                                       \
    {                                                                          \
        const unsigned* mrow = (mbp) + p8;                                     \
        _Pragma("unroll")                                                      \
        for (int j = 0; j < 24; j++) {                                         \
            unsigned m = mrow[j * 16] >> sh;                                   \
            float4 v;                                                          \
            v.x = (m & 1u) ? 1.0f : 0.0f;                                      \
            v.y = (m & 2u) ? 1.0f : 0.0f;                                      \
            v.z = (m & 4u) ? 1.0f : 0.0f;                                      \
            v.w = (m & 8u) ? 1.0f : 0.0f;                                      \
            *reinterpret_cast<float4*>(sg + (size_t)(j * 16) * TTOT + (tv)) = v;\
        }                                                                      \
    }
#define C_STEP(uu0, uu1, uu2, MASKOP)                                          \
    {                                                                          \
        const float w0v = fmaf(ALPHA_F, y0, (uu0));                            \
        const float w1v = fmaf(ALPHA_F, y1, (uu1));                            \
        const float w2v = fmaf(ALPHA_F, y2, (uu2));                            \
        const bool g01 = (w0v >= w1v), g02 = (w0v >= w2v), g12 = (w1v >= w2v); \
        const bool f0 = g01 & g02 & (w0v >= 1.0f);                             \
        const bool f1 = (!g01) & g12 & (w1v >= 1.0f);                          \
        const bool f2 = (!g02) & (!g12) & (w2v >= 1.0f);                       \
        y0 = w0v - (f0 ? 1.0f : 0.0f);                                         \
        y1 = w1v - (f1 ? 1.0f : 0.0f);                                         \
        y2 = w2v - (f2 ? 1.0f : 0.0f);                                         \
        MASKOP                                                                 \
    }

    // prime tile 0
    if (is_prod) {
        P_LD(start);
        P_ST(ub0);
    }
    __syncthreads();

    for (int i = 0; i < ntiles; i++) {
        const int t0 = start + i * TTILE;

        if (!is_prod) {
            // ---------- consumer: scan tile i via LDS.128 ----------
            const float* base = (i & 1 ? ub1 : ub0) + (3 * ptid) * ROWW;
            const float4* q0 = reinterpret_cast<const float4*>(base);
            const float4* q1 = reinterpret_cast<const float4*>(base + ROWW);
            const float4* q2 = reinterpret_cast<const float4*>(base + 2 * ROWW);
            if (i >= ci0) {
                unsigned m0 = 0u, m1 = 0u, m2 = 0u;
#pragma unroll
                for (int g = 0; g < 8; g++) {
                    const float4 a0v = q0[g];
                    const float4 a1v = q1[g];
                    const float4 a2v = q2[g];
                    C_STEP(a0v.x, a1v.x, a2v.x,
                           { if (f0) m0 |= 1u << (4*g+0); if (f1) m1 |= 1u << (4*g+0); if (f2) m2 |= 1u << (4*g+0); })
                    C_STEP(a0v.y, a1v.y, a2v.y,
                           { if (f0) m0 |= 1u << (4*g+1); if (f1) m1 |= 1u << (4*g+1); if (f2) m2 |= 1u << (4*g+1); })
                    C_STEP(a0v.z, a1v.z, a2v.z,
                           { if (f0) m0 |= 1u << (4*g+2); if (f1) m1 |= 1u << (4*g+2); if (f2) m2 |= 1u << (4*g+2); })
                    C_STEP(a0v.w, a1v.w, a2v.w,
                           { if (f0) m0 |= 1u << (4*g+3); if (f1) m1 |= 1u << (4*g+3); if (f2) m2 |= 1u << (4*g+3); })
                }
                unsigned* mw = (i & 1 ? mb1 : mb0) + 3 * ptid;
                mw[0] = m0; mw[1] = m1; mw[2] = m2;
            } else {
#pragma unroll
                for (int g = 0; g < 8; g++) {
                    const float4 a0v = q0[g];
                    const float4 a1v = q1[g];
                    const float4 a2v = q2[g];
                    C_STEP(a0v.x, a1v.x, a2v.x, )
                    C_STEP(a0v.y, a1v.y, a2v.y, )
                    C_STEP(a0v.z, a1v.z, a2v.z, )
                    C_STEP(a0v.w, a1v.w, a2v.w, )
                }
            }
        } else {
            // ---------- producer: LDG tile i+1, drain masks i-1, STS tile i+1
            if (i + 1 < ntiles) P_LD(t0 + TTILE);
            if (i >= 1 && i - 1 >= ci0)
                P_DRAIN((i - 1) & 1 ? mb1 : mb0, t0 - TTILE);   // overlaps LDG flight
            if (i + 1 < ntiles) P_ST((i + 1) & 1 ? ub1 : ub0);
        }

        __syncthreads();
    }

    // epilogue: drain last commit tile's masks
    if (is_prod) {
        const int ilast = ntiles - 1;
        P_DRAIN(ilast & 1 ? mb1 : mb0, start + ilast * TTILE);
    }
#undef P_LD
#undef P_ST
#undef P_DRAIN
#undef C_STEP
}

// ---------------------------------------------------------------------------
// Launch.
// ---------------------------------------------------------------------------
extern "C" void kernel_launch(void* const* d_in, const int* in_sizes, int n_in,
                              void* d_out, int out_size)
{
    const float* x  = (const float*)d_in[0];
    const float* w0 = (const float*)d_in[1];
    const float* w1 = (const float*)d_in[2];
    const float* w2 = (const float*)d_in[3];

    float* u = (float*)d_out;
    float* s = u + (size_t)BB * 3 * TTOT;

    cudaFuncSetAttribute(lif_kernel, cudaFuncAttributeMaxDynamicSharedMemorySize,
                         LIF_SMEM_BYTES);

    dim3 cgrid(BB, TTOT / 2048);
    conv_kernel<<<cgrid, 512>>>(x, w0, w1, w2, u);

    lif_kernel<<<NCHUNK * 2, 256, LIF_SMEM_BYTES>>>(u, s);
}